// round 14
// baseline (speedup 1.0000x reference)
#include <cuda_runtime.h>
#include <math.h>

#define B_    4
#define S_    4096
#define DIN_  512
#define DOUT_ 64
#define SCALE 0.015625f   // 1/sqrt(4096)

#define NPAIR   32
#define CHUNK_T 8
#define BLKS_PB 144
#define NBLKS   (B_ * BLKS_PB)      // 576

// Scratch. g_K/g_V stored with intra-row XOR swizzle:
//   word(row, d) = row*64 + (d ^ (((row&3)<<3) | (row&4)))
// g_Q plain row-major. All values tf32-rounded fp32.
__device__ float g_Q[B_ * S_ * DOUT_];
__device__ float g_K[B_ * S_ * DOUT_];
__device__ float g_V[B_ * S_ * DOUT_];
__device__ float g_Op[B_ * NPAIR * 8 * 128 * DOUT_];
__device__ float g_Lp[B_ * NPAIR * 8 * 128];
__device__ unsigned g_Wr[3 * DIN_ * DOUT_];   // W pre-rounded to tf32 bits

__device__ __forceinline__ unsigned f2tf32(float x) {
    unsigned r;
    asm("cvt.rna.tf32.f32 %0, %1;" : "=r"(r) : "f"(x));
    return r;
}

__device__ __forceinline__ void mma_tf32(float c[4], const unsigned a[4],
                                         unsigned b0, unsigned b1) {
    asm volatile(
        "mma.sync.aligned.m16n8k8.row.col.f32.tf32.tf32.f32 "
        "{%0,%1,%2,%3},{%4,%5,%6,%7},{%8,%9},{%0,%1,%2,%3};"
        : "+f"(c[0]), "+f"(c[1]), "+f"(c[2]), "+f"(c[3])
        : "r"(a[0]), "r"(a[1]), "r"(a[2]), "r"(a[3]), "r"(b0), "r"(b1));
}

// ---- bulk copy + mbarrier helpers -----------------------------------------
__device__ __forceinline__ void mbar_init(void* p, unsigned cnt) {
    unsigned a = (unsigned)__cvta_generic_to_shared(p);
    asm volatile("mbarrier.init.shared.b64 [%0], %1;" :: "r"(a), "r"(cnt) : "memory");
}
__device__ __forceinline__ void mbar_expect_tx(void* p, unsigned bytes) {
    unsigned a = (unsigned)__cvta_generic_to_shared(p);
    asm volatile("mbarrier.arrive.expect_tx.shared.b64 _, [%0], %1;"
                 :: "r"(a), "r"(bytes) : "memory");
}
__device__ __forceinline__ void bulk_g2s(void* sdst, const void* gsrc,
                                         unsigned bytes, void* mbar) {
    unsigned d = (unsigned)__cvta_generic_to_shared(sdst);
    unsigned m = (unsigned)__cvta_generic_to_shared(mbar);
    asm volatile(
        "cp.async.bulk.shared::cta.global.mbarrier::complete_tx::bytes [%0], [%1], %2, [%3];"
        :: "r"(d), "l"(gsrc), "r"(bytes), "r"(m) : "memory");
}
__device__ __forceinline__ void mbar_wait(void* p, unsigned phase) {
    unsigned a = (unsigned)__cvta_generic_to_shared(p);
    asm volatile(
        "{\n\t.reg .pred P;\n\t"
        "W%=:\n\t"
        "mbarrier.try_wait.parity.acquire.cta.shared::cta.b64 P, [%0], %1;\n\t"
        "@!P bra W%=;\n\t}"
        :: "r"(a), "r"(phase) : "memory");
}

// ---------------------------------------------------------------------------
// W prep: rna-round weights once (bit-identical to rounding on every use).
// ---------------------------------------------------------------------------
__global__ __launch_bounds__(256) void w_prep_kernel(
        const float* __restrict__ w0, const float* __restrict__ w1,
        const float* __restrict__ w2) {
    const int t = blockIdx.x * 256 + threadIdx.x;
    const int which = t >> 13;
    const int idx = t & 8191;
    const float* W = (which == 0) ? w0 : (which == 1) ? w1 : w2;
    float4 v = ((const float4*)W)[idx];
    uint4 u;
    u.x = f2tf32(v.x); u.y = f2tf32(v.y); u.z = f2tf32(v.z); u.w = f2tf32(v.w);
    ((uint4*)(g_Wr + which * DIN_ * DOUT_))[idx] = u;
}

// ---------------------------------------------------------------------------
// Projection GEMM. 128-row blocks, 128 threads = 4 warps x 32 rows.
// X: 3-stage smem + 2 register sets -> LDG(c+4) issued at iter c, consumed
// at iter c+2 (2-iteration gap covers ~600cyc DRAM latency; 2 chunks in
// flight). W: 2-stage, 1-ahead (L2-resident). Bit-identical numerics.
// which: 0 -> g_K (swizzled), 1 -> g_V (swizzled), 2 -> g_Q (plain).
// ---------------------------------------------------------------------------
#define PXS 36
#define PWS 72
#define PROJ_SMEM_BYTES ((3 * 128 * PXS + 2 * 32 * PWS) * 4)   // 73728

__global__ __launch_bounds__(128) void proj_mma_kernel(
        const float* __restrict__ x0, const float* __restrict__ x1,
        const float* __restrict__ x2) {
    extern __shared__ float smp[];
    float* Xst[3] = { smp, smp + 128 * PXS, smp + 2 * 128 * PXS };
    unsigned* Wst[2] = { (unsigned*)(smp + 3 * 128 * PXS),
                         (unsigned*)(smp + 3 * 128 * PXS) + 32 * PWS };

    const int which = blockIdx.y;
    const float* X = (which == 0) ? x0 : (which == 1) ? x1 : x2;
    const unsigned* Wr = g_Wr + which * DIN_ * DOUT_;
    float* dst = (which == 0) ? g_K : (which == 1) ? g_V : g_Q;

    const int m0   = blockIdx.x * 128;
    const int tid  = threadIdx.x;
    const int w    = tid >> 5;
    const int lane = tid & 31;
    const int g    = lane >> 2;
    const int tq   = lane & 3;

    float4 xr[2][8];
    uint4  wr[4];

    #define LDGX(k0_, set_) do {                                               \
        _Pragma("unroll")                                                      \
        for (int i_ = 0; i_ < 8; i_++) {                                       \
            int f_ = tid + i_ * 128;                                           \
            xr[set_][i_] = *(const float4*)(X + (size_t)(m0 + (f_ >> 3)) * DIN_\
                                              + (k0_) + (f_ & 7) * 4);         \
        }                                                                      \
    } while (0)

    #define STSX(st_, set_) do {                                               \
        float* Xc_ = Xst[st_];                                                 \
        _Pragma("unroll")                                                      \
        for (int i_ = 0; i_ < 8; i_++) {                                       \
            int f_ = tid + i_ * 128;                                           \
            *(float4*)(Xc_ + (f_ >> 3) * PXS + (f_ & 7) * 4) = xr[set_][i_];   \
        }                                                                      \
    } while (0)

    #define LDGW(k0_) do {                                                     \
        _Pragma("unroll")                                                      \
        for (int i_ = 0; i_ < 4; i_++) {                                       \
            int f_ = tid + i_ * 128;                                           \
            wr[i_] = *(const uint4*)(Wr + (size_t)((k0_) + (f_ >> 4)) * DOUT_  \
                                        + (f_ & 15) * 4);                      \
        }                                                                      \
    } while (0)

    #define STSW(buf_) do {                                                    \
        _Pragma("unroll")                                                      \
        for (int i_ = 0; i_ < 4; i_++) {                                       \
            int f_ = tid + i_ * 128;                                           \
            *(uint4*)(Wst[buf_] + (f_ >> 4) * PWS + (f_ & 15) * 4) = wr[i_];   \
        }                                                                      \
    } while (0)

    // prologue: stages 0,1 filled; xr[0]=chunk2, xr[1]=chunk3, wr=chunk1
    LDGX(0, 0);  LDGW(0);
    STSX(0, 0);  STSW(0);
    LDGX(32, 1); LDGW(32);
    STSX(1, 1);
    LDGX(64, 0);
    LDGX(96, 1);
    __syncthreads();

    float acc[2][8][4];
    #pragma unroll
    for (int m2 = 0; m2 < 2; m2++)
        #pragma unroll
        for (int nt = 0; nt < 8; nt++)
            #pragma unroll
            for (int j = 0; j < 4; j++) acc[m2][nt][j] = 0.0f;

    #pragma unroll 1
    for (int c = 0; c < 16; c++) {
        // stage future chunks FIRST (writes target stages not read this iter)
        if (c + 2 < 16) STSX((c + 2) % 3, c & 1);      // consumes xr[c&1]=chunk c+2
        if (c + 1 < 16) STSW((c + 1) & 1);             // consumes wr = chunk c+1
        if (c + 2 < 16) LDGW((c + 2) * 32);            // wr <- chunk c+2
        if (c + 4 < 16) LDGX((c + 4) * 32, c & 1);     // xr[c&1] <- chunk c+4

        const float*    Xc = Xst[c % 3];
        const unsigned* Wc = Wst[c & 1];

        #pragma unroll
        for (int kk = 0; kk < 4; kk++) {
            unsigned a0[4], a1[4];
            const int q0 = w * 32 + g;
            a0[0] = f2tf32(Xc[q0 * PXS + kk * 8 + tq]);
            a0[1] = f2tf32(Xc[(q0 + 8) * PXS + kk * 8 + tq]);
            a0[2] = f2tf32(Xc[q0 * PXS + kk * 8 + tq + 4]);
            a0[3] = f2tf32(Xc[(q0 + 8) * PXS + kk * 8 + tq + 4]);
            a1[0] = f2tf32(Xc[(q0 + 16) * PXS + kk * 8 + tq]);
            a1[1] = f2tf32(Xc[(q0 + 24) * PXS + kk * 8 + tq]);
            a1[2] = f2tf32(Xc[(q0 + 16) * PXS + kk * 8 + tq + 4]);
            a1[3] = f2tf32(Xc[(q0 + 24) * PXS + kk * 8 + tq + 4]);
            #pragma unroll
            for (int nt = 0; nt < 8; nt++) {
                unsigned b0 = Wc[(kk * 8 + tq) * PWS + nt * 8 + g];
                unsigned b1 = Wc[(kk * 8 + tq + 4) * PWS + nt * 8 + g];
                mma_tf32(acc[0][nt], a0, b0, b1);
                mma_tf32(acc[1][nt], a1, b0, b1);
            }
        }

        if (c < 15) __syncthreads();
    }
    #undef LDGX
    #undef STSX
    #undef LDGW
    #undef STSW

    #pragma unroll
    for (int m2 = 0; m2 < 2; m2++) {
        #pragma unroll
        for (int nt = 0; nt < 8; nt++) {
            #pragma unroll
            for (int rr = 0; rr < 2; rr++) {
                const int row = m0 + w * 32 + m2 * 16 + g + rr * 8;
                const int d   = nt * 8 + tq * 2;
                float2 v;
                v.x = __uint_as_float(f2tf32(acc[m2][nt][rr * 2 + 0]));
                v.y = __uint_as_float(f2tf32(acc[m2][nt][rr * 2 + 1]));
                int dd = (which == 2) ? d : (d ^ (((row & 3) << 3) | (row & 4)));
                *(float2*)(dst + (size_t)row * DOUT_ + dd) = v;
            }
        }
    }
}

// ---------------------------------------------------------------------------
// Split-K flash attention partial (EXACT R12 version — best known).
// ---------------------------------------------------------------------------
#define PSS 68
#define ATTN_SMEM_BYTES ((4 * 4096 + 128 * PSS) * 4 + 16)   // 100368

__global__ __launch_bounds__(128) void attn_part_kernel() {
    extern __shared__ unsigned sm[];
    unsigned* Kb[2] = { sm,        sm + 4096 };
    unsigned* Vb[2] = { sm + 8192, sm + 12288 };
    unsigned* Ps    = sm + 16384;
    unsigned long long* mb = (unsigned long long*)(Ps + 128 * PSS);

    const int tid  = threadIdx.x;
    const int w    = tid >> 5;
    const int lane = tid & 31;
    const int g    = lane >> 2;
    const int tq   = lane & 3;

    const int b = blockIdx.x / BLKS_PB;
    int f = blockIdx.x % BLKS_PB;
    int gp = 0;
    while (f >= 2 * (gp + 1) * (gp + 2)) gp++;
    const int r  = f - 2 * gp * (gp + 1);
    const int p  = 4 * gp + r / (gp + 1);
    const int c  = r % (gp + 1);
    const int ntiles = min(CHUNK_T, 2 * p + 2 - CHUNK_T * c);

    const float* Qg = g_Q + (size_t)b * S_ * DOUT_ + (size_t)p * 128 * DOUT_;
    const float* Kg = g_K + (size_t)b * S_ * DOUT_ + (size_t)c * CHUNK_T * 64 * DOUT_;
    const float* Vg = g_V + (size_t)b * S_ * DOUT_ + (size_t)c * CHUNK_T * 64 * DOUT_;

    #define ISSUE(kt_) do {                                                   \
        int buf_ = (kt_) & 1;                                                 \
        mbar_expect_tx(mb + buf_, 32768u);                                    \
        bulk_g2s(Kb[buf_], Kg + (size_t)(kt_) * 64 * DOUT_, 16384u, mb + buf_);\
        bulk_g2s(Vb[buf_], Vg + (size_t)(kt_) * 64 * DOUT_, 16384u, mb + buf_);\
    } while (0)

    if (tid == 0) { mbar_init(mb, 1); mbar_init(mb + 1, 1); }
    __syncthreads();
    if (tid == 0) { ISSUE(0); if (ntiles > 1) ISSUE(1); }

    #pragma unroll
    for (int t = 0; t < 16; t++) {
        int ff = tid + t * 128;
        int rr = ff >> 4, s4 = ff & 15;
        float4 qv = *(const float4*)(Qg + (size_t)rr * DOUT_ + s4 * 4);
        unsigned* d = Ps + rr * PSS + s4 * 4;
        d[0] = __float_as_uint(qv.x); d[1] = __float_as_uint(qv.y);
        d[2] = __float_as_uint(qv.z); d[3] = __float_as_uint(qv.w);
    }
    __syncthreads();

    unsigned qa[2][8][4];
    #pragma unroll
    for (int m2 = 0; m2 < 2; m2++) {
        const int q0 = w * 32 + m2 * 16 + g;
        #pragma unroll
        for (int kk = 0; kk < 8; kk++) {
            qa[m2][kk][0] = Ps[q0 * PSS + kk * 8 + tq];
            qa[m2][kk][1] = Ps[(q0 + 8) * PSS + kk * 8 + tq];
            qa[m2][kk][2] = Ps[q0 * PSS + kk * 8 + tq + 4];
            qa[m2][kk][3] = Ps[(q0 + 8) * PSS + kk * 8 + tq + 4];
        }
    }

    float o[2][8][4];
    #pragma unroll
    for (int m2 = 0; m2 < 2; m2++)
        #pragma unroll
        for (int nt = 0; nt < 8; nt++)
            #pragma unroll
            for (int j = 0; j < 4; j++) o[m2][nt][j] = 0.0f;
    float l[2][2] = {{0.f, 0.f}, {0.f, 0.f}};

    const int swk  = ((g & 3) << 3) | (g & 4);
    const int swv0 = tq << 3;
    const int swv1 = (tq << 3) | 4;

    #pragma unroll 1
    for (int kt = 0; kt < ntiles; kt++) {
        const int kbase = (c * CHUNK_T + kt) * 64;

        mbar_wait(mb + (kt & 1), (kt >> 1) & 1);
        const unsigned* Ks = Kb[kt & 1];
        const unsigned* Vs = Vb[kt & 1];

        float sacc[2][8][4];
        #pragma unroll
        for (int m2 = 0; m2 < 2; m2++)
            #pragma unroll
            for (int nt = 0; nt < 8; nt++)
                #pragma unroll
                for (int j = 0; j < 4; j++) sacc[m2][nt][j] = 0.0f;

        #pragma unroll
        for (int kk = 0; kk < 8; kk++) {
            #pragma unroll
            for (int nt = 0; nt < 8; nt++) {
                unsigned b0 = Ks[(nt * 8 + g) * 64 + ((kk * 8 + tq) ^ swk)];
                unsigned b1 = Ks[(nt * 8 + g) * 64 + ((kk * 8 + tq + 4) ^ swk)];
                mma_tf32(sacc[0][nt], qa[0][kk], b0, b1);
                mma_tf32(sacc[1][nt], qa[1][kk], b0, b1);
            }
        }

        #pragma unroll
        for (int m2 = 0; m2 < 2; m2++) {
            const int pr    = w * 32 + m2 * 16 + g;
            const int row0g = p * 128 + pr;
            const int row1g = row0g + 8;
            const bool need_mask = (kbase + 63 > row0g);
            #pragma unroll
            for (int nt = 0; nt < 8; nt++) {
                float s00 = sacc[m2][nt][0] * SCALE;
                float s01 = sacc[m2][nt][1] * SCALE;
                float s10 = sacc[m2][nt][2] * SCALE;
                float s11 = sacc[m2][nt][3] * SCALE;
                float p00 = fmaf(s00, fmaf(s00, 0.5f, 1.0f), 1.0f);
                float p01 = fmaf(s01, fmaf(s01, 0.5f, 1.0f), 1.0f);
                float p10 = fmaf(s10, fmaf(s10, 0.5f, 1.0f), 1.0f);
                float p11 = fmaf(s11, fmaf(s11, 0.5f, 1.0f), 1.0f);
                if (need_mask) {
                    int c0 = kbase + nt * 8 + tq * 2;
                    int c1 = c0 + 1;
                    if (c0 > row0g) p00 = 0.0f;
                    if (c1 > row0g) p01 = 0.0f;
                    if (c0 > row1g) p10 = 0.0f;
                    if (c1 > row1g) p11 = 0.0f;
                }
                l[m2][0] += p00 + p01;
                l[m2][1] += p10 + p11;
                uint2 u0; u0.x = f2tf32(p00); u0.y = f2tf32(p01);
                uint2 u1; u1.x = f2tf32(p10); u1.y = f2tf32(p11);
                *(uint2*)(Ps + pr * PSS + nt * 8 + tq * 2)       = u0;
                *(uint2*)(Ps + (pr + 8) * PSS + nt * 8 + tq * 2) = u1;
            }
        }
        __syncwarp();

        #pragma unroll
        for (int kk = 0; kk < 8; kk++) {
            unsigned pa0[4], pa1[4];
            const int pr0 = w * 32 + g;
            const int pr1 = pr0 + 16;
            pa0[0] = Ps[pr0 * PSS + kk * 8 + tq];
            pa0[1] = Ps[(pr0 + 8) * PSS + kk * 8 + tq];
            pa0[2] = Ps[pr0 * PSS + kk * 8 + tq + 4];
            pa0[3] = Ps[(pr0 + 8) * PSS + kk * 8 + tq + 4];
            pa1[0] = Ps[pr1 * PSS + kk * 8 + tq];
            pa1[1] = Ps[(pr1 + 8) * PSS + kk * 8 + tq];
            pa1[2] = Ps[pr1 * PSS + kk * 8 + tq + 4];
            pa1[3] = Ps[(pr1 + 8) * PSS + kk * 8 + tq + 4];
            #pragma unroll
            for (int nt = 0; nt < 8; nt++) {
                unsigned b0 = Vs[(kk * 8 + tq) * 64     + ((nt * 8 + g) ^ swv0)];
                unsigned b1 = Vs[(kk * 8 + tq + 4) * 64 + ((nt * 8 + g) ^ swv1)];
                mma_tf32(o[0][nt], pa0, b0, b1);
                mma_tf32(o[1][nt], pa1, b0, b1);
            }
        }

        __syncthreads();
        if (tid == 0 && kt + 2 < ntiles) ISSUE(kt + 2);
    }
    #undef ISSUE

    #pragma unroll
    for (int m2 = 0; m2 < 2; m2++) {
        #pragma unroll
        for (int off = 1; off <= 2; off <<= 1) {
            l[m2][0] += __shfl_xor_sync(0xffffffffu, l[m2][0], off);
            l[m2][1] += __shfl_xor_sync(0xffffffffu, l[m2][1], off);
        }
    }

    const size_t pbase = ((size_t)(b * NPAIR + p) * 8 + c);
    float* Op = g_Op + pbase * 128 * DOUT_;
    float* Lp = g_Lp + pbase * 128;

    #pragma unroll
    for (int m2 = 0; m2 < 2; m2++) {
        const int pr = w * 32 + m2 * 16 + g;
        if (tq == 0) {
            Lp[pr]     = l[m2][0];
            Lp[pr + 8] = l[m2][1];
        }
        #pragma unroll
        for (int nt = 0; nt < 8; nt++) {
            float2 v0 = make_float2(o[m2][nt][0], o[m2][nt][1]);
            float2 v1 = make_float2(o[m2][nt][2], o[m2][nt][3]);
            *(float2*)(Op + (size_t)pr * DOUT_ + nt * 8 + tq * 2)       = v0;
            *(float2*)(Op + (size_t)(pr + 8) * DOUT_ + nt * 8 + tq * 2) = v1;
        }
    }
}

// ---------------------------------------------------------------------------
// Combine (warp-parallel): one warp per (row, 16-col quarter).
// lane = (c = lane&7, j = lane>>3): each lane loads ONE chunk's float4 ->
// all loads issue in parallel across lanes; tree-reduce over c via shfl_xor.
// ---------------------------------------------------------------------------
__global__ __launch_bounds__(256) void attn_combine_kernel(float* __restrict__ out) {
    const int gw   = (blockIdx.x * 256 + threadIdx.x) >> 5;   // 0..65535
    const int lane = threadIdx.x & 31;
    const int R    = gw >> 2;          // row 0..16383
    const int hq   = gw & 3;           // 16-col quarter
    const int b    = R >> 12;
    const int q    = R & 4095;
    const int p    = q >> 7;
    const int rw   = q & 127;
    const int nch  = (p >> 2) + 1;
    const int c    = lane & 7;
    const int j    = lane >> 3;

    const size_t pb = (size_t)(b * NPAIR + p) * 8;
    float4 v = make_float4(0.f, 0.f, 0.f, 0.f);
    float  ls = 0.0f;
    if (c < nch) {
        const float* Op = g_Op + (pb + c) * 128 * DOUT_
                        + (size_t)rw * DOUT_ + hq * 16 + j * 4;
        v = *(const float4*)Op;
        if (j == 0) ls = g_Lp[(pb + c) * 128 + rw];
    }

    #pragma unroll
    for (int off = 1; off <= 4; off <<= 1) {
        v.x += __shfl_xor_sync(0xffffffffu, v.x, off);
        v.y += __shfl_xor_sync(0xffffffffu, v.y, off);
        v.z += __shfl_xor_sync(0xffffffffu, v.z, off);
        v.w += __shfl_xor_sync(0xffffffffu, v.w, off);
        ls  += __shfl_xor_sync(0xffffffffu, ls, off);
    }
    const float lsum = __shfl_sync(0xffffffffu, ls, 0);

    if (c == 0) {
        const float inv = 1.0f / lsum;
        float4 ov = make_float4(v.x * inv, v.y * inv, v.z * inv, v.w * inv);
        *(float4*)(out + (size_t)R * DOUT_ + hq * 16 + j * 4) = ov;
    }
}

// ---------------------------------------------------------------------------
extern "C" void kernel_launch(void* const* d_in, const int* in_sizes, int n_in,
                              void* d_out, int out_size) {
    const float* x_k = (const float*)d_in[0];
    const float* x_v = (const float*)d_in[1];
    const float* x_q = (const float*)d_in[2];
    const float* Wk  = (const float*)d_in[3];
    const float* Wq  = (const float*)d_in[4];
    const float* Wv  = (const float*)d_in[5];
    float* out = (float*)d_out;

    cudaFuncSetAttribute(proj_mma_kernel, cudaFuncAttributeMaxDynamicSharedMemorySize,
                         PROJ_SMEM_BYTES);
    cudaFuncSetAttribute(attn_part_kernel, cudaFuncAttributeMaxDynamicSharedMemorySize,
                         ATTN_SMEM_BYTES);

    w_prep_kernel<<<96, 256>>>(Wk, Wv, Wq);
    proj_mma_kernel<<<dim3(128, 3), 128, PROJ_SMEM_BYTES>>>(x_k, x_v, x_q);
    attn_part_kernel<<<NBLKS, 128, ATTN_SMEM_BYTES>>>();
    attn_combine_kernel<<<8192, 256>>>(out);
}

// round 15
// speedup vs baseline: 1.3568x; 1.3568x over previous
#include <cuda_runtime.h>
#include <math.h>

#define B_    4
#define S_    4096
#define DIN_  512
#define DOUT_ 64
#define SCALE 0.015625f   // 1/sqrt(4096)

#define NPAIR   32
#define CHUNK_T 8
#define BLKS_PB 144
#define NBLKS   (B_ * BLKS_PB)      // 576

// Scratch. g_K/g_V stored with intra-row XOR swizzle:
//   word(row, d) = row*64 + (d ^ (((row&3)<<3) | (row&4)))
// g_Q plain row-major. All values tf32-rounded fp32.
__device__ float g_Q[B_ * S_ * DOUT_];
__device__ float g_K[B_ * S_ * DOUT_];
__device__ float g_V[B_ * S_ * DOUT_];
__device__ float g_Op[B_ * NPAIR * 8 * 128 * DOUT_];
__device__ float g_Lp[B_ * NPAIR * 8 * 128];
__device__ unsigned g_Wr[3 * DIN_ * DOUT_];   // W pre-rounded to tf32 bits

__device__ __forceinline__ unsigned f2tf32(float x) {
    unsigned r;
    asm("cvt.rna.tf32.f32 %0, %1;" : "=r"(r) : "f"(x));
    return r;
}

__device__ __forceinline__ void mma_tf32(float c[4], const unsigned a[4],
                                         unsigned b0, unsigned b1) {
    asm volatile(
        "mma.sync.aligned.m16n8k8.row.col.f32.tf32.tf32.f32 "
        "{%0,%1,%2,%3},{%4,%5,%6,%7},{%8,%9},{%0,%1,%2,%3};"
        : "+f"(c[0]), "+f"(c[1]), "+f"(c[2]), "+f"(c[3])
        : "r"(a[0]), "r"(a[1]), "r"(a[2]), "r"(a[3]), "r"(b0), "r"(b1));
}

// ---- bulk copy + mbarrier helpers -----------------------------------------
__device__ __forceinline__ void mbar_init(void* p, unsigned cnt) {
    unsigned a = (unsigned)__cvta_generic_to_shared(p);
    asm volatile("mbarrier.init.shared.b64 [%0], %1;" :: "r"(a), "r"(cnt) : "memory");
}
__device__ __forceinline__ void mbar_expect_tx(void* p, unsigned bytes) {
    unsigned a = (unsigned)__cvta_generic_to_shared(p);
    asm volatile("mbarrier.arrive.expect_tx.shared.b64 _, [%0], %1;"
                 :: "r"(a), "r"(bytes) : "memory");
}
__device__ __forceinline__ void bulk_g2s(void* sdst, const void* gsrc,
                                         unsigned bytes, void* mbar) {
    unsigned d = (unsigned)__cvta_generic_to_shared(sdst);
    unsigned m = (unsigned)__cvta_generic_to_shared(mbar);
    asm volatile(
        "cp.async.bulk.shared::cta.global.mbarrier::complete_tx::bytes [%0], [%1], %2, [%3];"
        :: "r"(d), "l"(gsrc), "r"(bytes), "r"(m) : "memory");
}
__device__ __forceinline__ void mbar_wait(void* p, unsigned phase) {
    unsigned a = (unsigned)__cvta_generic_to_shared(p);
    asm volatile(
        "{\n\t.reg .pred P;\n\t"
        "W%=:\n\t"
        "mbarrier.try_wait.parity.acquire.cta.shared::cta.b64 P, [%0], %1;\n\t"
        "@!P bra W%=;\n\t}"
        :: "r"(a), "r"(phase) : "memory");
}

// ---------------------------------------------------------------------------
// W prep: rna-round weights once (bit-identical to rounding on every use).
// ---------------------------------------------------------------------------
__global__ __launch_bounds__(256) void w_prep_kernel(
        const float* __restrict__ w0, const float* __restrict__ w1,
        const float* __restrict__ w2) {
    const int t = blockIdx.x * 256 + threadIdx.x;
    const int which = t >> 13;
    const int idx = t & 8191;
    const float* W = (which == 0) ? w0 : (which == 1) ? w1 : w2;
    float4 v = ((const float4*)W)[idx];
    uint4 u;
    u.x = f2tf32(v.x); u.y = f2tf32(v.y); u.z = f2tf32(v.z); u.w = f2tf32(v.w);
    ((uint4*)(g_Wr + which * DIN_ * DOUT_))[idx] = u;
}

// ---------------------------------------------------------------------------
// Projection GEMM (exact R12 version — best measured). 128-row blocks,
// 128 threads = 4 warps x 32 rows (2 m16 blocks each).
// which: 0 -> g_K (swizzled), 1 -> g_V (swizzled), 2 -> g_Q (plain).
// ---------------------------------------------------------------------------
#define PXS 36
#define PWS 72
#define PROJ_SMEM_BYTES ((2 * 128 * PXS + 2 * 32 * PWS) * 4)   // 55296

__global__ __launch_bounds__(128) void proj_mma_kernel(
        const float* __restrict__ x0, const float* __restrict__ x1,
        const float* __restrict__ x2) {
    extern __shared__ float smp[];
    float*    Xb[2] = { smp, smp + 128 * PXS };
    unsigned* Wb[2] = { (unsigned*)(smp + 2 * 128 * PXS),
                        (unsigned*)(smp + 2 * 128 * PXS) + 32 * PWS };

    const int which = blockIdx.y;
    const float* X = (which == 0) ? x0 : (which == 1) ? x1 : x2;
    const unsigned* Wr = g_Wr + which * DIN_ * DOUT_;
    float* dst = (which == 0) ? g_K : (which == 1) ? g_V : g_Q;

    const int m0   = blockIdx.x * 128;
    const int tid  = threadIdx.x;
    const int w    = tid >> 5;
    const int lane = tid & 31;
    const int g    = lane >> 2;
    const int tq   = lane & 3;

    float4 xr[8];
    uint4  wr[4];

    #define LDG_CHUNK(k0_) do {                                               \
        _Pragma("unroll")                                                     \
        for (int i_ = 0; i_ < 8; i_++) {                                      \
            int f_ = tid + i_ * 128;                                          \
            xr[i_] = *(const float4*)(X + (size_t)(m0 + (f_ >> 3)) * DIN_     \
                                        + (k0_) + (f_ & 7) * 4);              \
        }                                                                     \
        _Pragma("unroll")                                                     \
        for (int i_ = 0; i_ < 4; i_++) {                                      \
            int f_ = tid + i_ * 128;                                          \
            wr[i_] = *(const uint4*)(Wr + (size_t)((k0_) + (f_ >> 4)) * DOUT_ \
                                        + (f_ & 15) * 4);                     \
        }                                                                     \
    } while (0)

    #define STS_CHUNK(buf_) do {                                              \
        _Pragma("unroll")                                                     \
        for (int i_ = 0; i_ < 8; i_++) {                                      \
            int f_ = tid + i_ * 128;                                          \
            *(float4*)(Xb[buf_] + (f_ >> 3) * PXS + (f_ & 7) * 4) = xr[i_];   \
        }                                                                     \
        _Pragma("unroll")                                                     \
        for (int i_ = 0; i_ < 4; i_++) {                                      \
            int f_ = tid + i_ * 128;                                          \
            *(uint4*)(Wb[buf_] + (f_ >> 4) * PWS + (f_ & 15) * 4) = wr[i_];   \
        }                                                                     \
    } while (0)

    LDG_CHUNK(0);
    STS_CHUNK(0);
    LDG_CHUNK(32);
    __syncthreads();

    float acc[2][8][4];
    #pragma unroll
    for (int m2 = 0; m2 < 2; m2++)
        #pragma unroll
        for (int nt = 0; nt < 8; nt++)
            #pragma unroll
            for (int j = 0; j < 4; j++) acc[m2][nt][j] = 0.0f;

    #pragma unroll 2
    for (int c = 0; c < 16; c++) {
        const int cur = c & 1;
        const float* Xc = Xb[cur];
        const unsigned* Wc = Wb[cur];

        #pragma unroll
        for (int kk = 0; kk < 4; kk++) {
            unsigned a0[4], a1[4];
            const int q0 = w * 32 + g;
            a0[0] = f2tf32(Xc[q0 * PXS + kk * 8 + tq]);
            a0[1] = f2tf32(Xc[(q0 + 8) * PXS + kk * 8 + tq]);
            a0[2] = f2tf32(Xc[q0 * PXS + kk * 8 + tq + 4]);
            a0[3] = f2tf32(Xc[(q0 + 8) * PXS + kk * 8 + tq + 4]);
            a1[0] = f2tf32(Xc[(q0 + 16) * PXS + kk * 8 + tq]);
            a1[1] = f2tf32(Xc[(q0 + 24) * PXS + kk * 8 + tq]);
            a1[2] = f2tf32(Xc[(q0 + 16) * PXS + kk * 8 + tq + 4]);
            a1[3] = f2tf32(Xc[(q0 + 24) * PXS + kk * 8 + tq + 4]);
            #pragma unroll
            for (int nt = 0; nt < 8; nt++) {
                unsigned b0 = Wc[(kk * 8 + tq) * PWS + nt * 8 + g];
                unsigned b1 = Wc[(kk * 8 + tq + 4) * PWS + nt * 8 + g];
                mma_tf32(acc[0][nt], a0, b0, b1);
                mma_tf32(acc[1][nt], a1, b0, b1);
            }
        }

        if (c < 15) {
            STS_CHUNK(cur ^ 1);
            if (c < 14) LDG_CHUNK((c + 2) * 32);
            __syncthreads();
        }
    }
    #undef LDG_CHUNK
    #undef STS_CHUNK

    #pragma unroll
    for (int m2 = 0; m2 < 2; m2++) {
        #pragma unroll
        for (int nt = 0; nt < 8; nt++) {
            #pragma unroll
            for (int rr = 0; rr < 2; rr++) {
                const int row = m0 + w * 32 + m2 * 16 + g + rr * 8;
                const int d   = nt * 8 + tq * 2;
                float2 v;
                v.x = __uint_as_float(f2tf32(acc[m2][nt][rr * 2 + 0]));
                v.y = __uint_as_float(f2tf32(acc[m2][nt][rr * 2 + 1]));
                int dd = (which == 2) ? d : (d ^ (((row & 3) << 3) | (row & 4)));
                *(float2*)(dst + (size_t)row * DOUT_ + dd) = v;
            }
        }
    }
}

// ---------------------------------------------------------------------------
// Split-K flash attention partial (exact R12 version — best measured).
// ---------------------------------------------------------------------------
#define PSS 68
#define ATTN_SMEM_BYTES ((4 * 4096 + 128 * PSS) * 4 + 16)   // 100368

__global__ __launch_bounds__(128) void attn_part_kernel() {
    extern __shared__ unsigned sm[];
    unsigned* Kb[2] = { sm,        sm + 4096 };
    unsigned* Vb[2] = { sm + 8192, sm + 12288 };
    unsigned* Ps    = sm + 16384;
    unsigned long long* mb = (unsigned long long*)(Ps + 128 * PSS);

    const int tid  = threadIdx.x;
    const int w    = tid >> 5;
    const int lane = tid & 31;
    const int g    = lane >> 2;
    const int tq   = lane & 3;

    const int b = blockIdx.x / BLKS_PB;
    int f = blockIdx.x % BLKS_PB;
    int gp = 0;
    while (f >= 2 * (gp + 1) * (gp + 2)) gp++;
    const int r  = f - 2 * gp * (gp + 1);
    const int p  = 4 * gp + r / (gp + 1);
    const int c  = r % (gp + 1);
    const int ntiles = min(CHUNK_T, 2 * p + 2 - CHUNK_T * c);

    const float* Qg = g_Q + (size_t)b * S_ * DOUT_ + (size_t)p * 128 * DOUT_;
    const float* Kg = g_K + (size_t)b * S_ * DOUT_ + (size_t)c * CHUNK_T * 64 * DOUT_;
    const float* Vg = g_V + (size_t)b * S_ * DOUT_ + (size_t)c * CHUNK_T * 64 * DOUT_;

    #define ISSUE(kt_) do {                                                   \
        int buf_ = (kt_) & 1;                                                 \
        mbar_expect_tx(mb + buf_, 32768u);                                    \
        bulk_g2s(Kb[buf_], Kg + (size_t)(kt_) * 64 * DOUT_, 16384u, mb + buf_);\
        bulk_g2s(Vb[buf_], Vg + (size_t)(kt_) * 64 * DOUT_, 16384u, mb + buf_);\
    } while (0)

    if (tid == 0) { mbar_init(mb, 1); mbar_init(mb + 1, 1); }
    __syncthreads();
    if (tid == 0) { ISSUE(0); if (ntiles > 1) ISSUE(1); }

    #pragma unroll
    for (int t = 0; t < 16; t++) {
        int ff = tid + t * 128;
        int rr = ff >> 4, s4 = ff & 15;
        float4 qv = *(const float4*)(Qg + (size_t)rr * DOUT_ + s4 * 4);
        unsigned* d = Ps + rr * PSS + s4 * 4;
        d[0] = __float_as_uint(qv.x); d[1] = __float_as_uint(qv.y);
        d[2] = __float_as_uint(qv.z); d[3] = __float_as_uint(qv.w);
    }
    __syncthreads();

    unsigned qa[2][8][4];
    #pragma unroll
    for (int m2 = 0; m2 < 2; m2++) {
        const int q0 = w * 32 + m2 * 16 + g;
        #pragma unroll
        for (int kk = 0; kk < 8; kk++) {
            qa[m2][kk][0] = Ps[q0 * PSS + kk * 8 + tq];
            qa[m2][kk][1] = Ps[(q0 + 8) * PSS + kk * 8 + tq];
            qa[m2][kk][2] = Ps[q0 * PSS + kk * 8 + tq + 4];
            qa[m2][kk][3] = Ps[(q0 + 8) * PSS + kk * 8 + tq + 4];
        }
    }

    float o[2][8][4];
    #pragma unroll
    for (int m2 = 0; m2 < 2; m2++)
        #pragma unroll
        for (int nt = 0; nt < 8; nt++)
            #pragma unroll
            for (int j = 0; j < 4; j++) o[m2][nt][j] = 0.0f;
    float l[2][2] = {{0.f, 0.f}, {0.f, 0.f}};

    const int swk  = ((g & 3) << 3) | (g & 4);
    const int swv0 = tq << 3;
    const int swv1 = (tq << 3) | 4;

    #pragma unroll 1
    for (int kt = 0; kt < ntiles; kt++) {
        const int kbase = (c * CHUNK_T + kt) * 64;

        mbar_wait(mb + (kt & 1), (kt >> 1) & 1);
        const unsigned* Ks = Kb[kt & 1];
        const unsigned* Vs = Vb[kt & 1];

        float sacc[2][8][4];
        #pragma unroll
        for (int m2 = 0; m2 < 2; m2++)
            #pragma unroll
            for (int nt = 0; nt < 8; nt++)
                #pragma unroll
                for (int j = 0; j < 4; j++) sacc[m2][nt][j] = 0.0f;

        #pragma unroll
        for (int kk = 0; kk < 8; kk++) {
            #pragma unroll
            for (int nt = 0; nt < 8; nt++) {
                unsigned b0 = Ks[(nt * 8 + g) * 64 + ((kk * 8 + tq) ^ swk)];
                unsigned b1 = Ks[(nt * 8 + g) * 64 + ((kk * 8 + tq + 4) ^ swk)];
                mma_tf32(sacc[0][nt], qa[0][kk], b0, b1);
                mma_tf32(sacc[1][nt], qa[1][kk], b0, b1);
            }
        }

        #pragma unroll
        for (int m2 = 0; m2 < 2; m2++) {
            const int pr    = w * 32 + m2 * 16 + g;
            const int row0g = p * 128 + pr;
            const int row1g = row0g + 8;
            const bool need_mask = (kbase + 63 > row0g);
            #pragma unroll
            for (int nt = 0; nt < 8; nt++) {
                float s00 = sacc[m2][nt][0] * SCALE;
                float s01 = sacc[m2][nt][1] * SCALE;
                float s10 = sacc[m2][nt][2] * SCALE;
                float s11 = sacc[m2][nt][3] * SCALE;
                float p00 = fmaf(s00, fmaf(s00, 0.5f, 1.0f), 1.0f);
                float p01 = fmaf(s01, fmaf(s01, 0.5f, 1.0f), 1.0f);
                float p10 = fmaf(s10, fmaf(s10, 0.5f, 1.0f), 1.0f);
                float p11 = fmaf(s11, fmaf(s11, 0.5f, 1.0f), 1.0f);
                if (need_mask) {
                    int c0 = kbase + nt * 8 + tq * 2;
                    int c1 = c0 + 1;
                    if (c0 > row0g) p00 = 0.0f;
                    if (c1 > row0g) p01 = 0.0f;
                    if (c0 > row1g) p10 = 0.0f;
                    if (c1 > row1g) p11 = 0.0f;
                }
                l[m2][0] += p00 + p01;
                l[m2][1] += p10 + p11;
                uint2 u0; u0.x = f2tf32(p00); u0.y = f2tf32(p01);
                uint2 u1; u1.x = f2tf32(p10); u1.y = f2tf32(p11);
                *(uint2*)(Ps + pr * PSS + nt * 8 + tq * 2)       = u0;
                *(uint2*)(Ps + (pr + 8) * PSS + nt * 8 + tq * 2) = u1;
            }
        }
        __syncwarp();

        #pragma unroll
        for (int kk = 0; kk < 8; kk++) {
            unsigned pa0[4], pa1[4];
            const int pr0 = w * 32 + g;
            const int pr1 = pr0 + 16;
            pa0[0] = Ps[pr0 * PSS + kk * 8 + tq];
            pa0[1] = Ps[(pr0 + 8) * PSS + kk * 8 + tq];
            pa0[2] = Ps[pr0 * PSS + kk * 8 + tq + 4];
            pa0[3] = Ps[(pr0 + 8) * PSS + kk * 8 + tq + 4];
            pa1[0] = Ps[pr1 * PSS + kk * 8 + tq];
            pa1[1] = Ps[(pr1 + 8) * PSS + kk * 8 + tq];
            pa1[2] = Ps[pr1 * PSS + kk * 8 + tq + 4];
            pa1[3] = Ps[(pr1 + 8) * PSS + kk * 8 + tq + 4];
            #pragma unroll
            for (int nt = 0; nt < 8; nt++) {
                unsigned b0 = Vs[(kk * 8 + tq) * 64     + ((nt * 8 + g) ^ swv0)];
                unsigned b1 = Vs[(kk * 8 + tq + 4) * 64 + ((nt * 8 + g) ^ swv1)];
                mma_tf32(o[0][nt], pa0, b0, b1);
                mma_tf32(o[1][nt], pa1, b0, b1);
            }
        }

        __syncthreads();
        if (tid == 0 && kt + 2 < ntiles) ISSUE(kt + 2);
    }
    #undef ISSUE

    #pragma unroll
    for (int m2 = 0; m2 < 2; m2++) {
        #pragma unroll
        for (int off = 1; off <= 2; off <<= 1) {
            l[m2][0] += __shfl_xor_sync(0xffffffffu, l[m2][0], off);
            l[m2][1] += __shfl_xor_sync(0xffffffffu, l[m2][1], off);
        }
    }

    const size_t pbase = ((size_t)(b * NPAIR + p) * 8 + c);
    float* Op = g_Op + pbase * 128 * DOUT_;
    float* Lp = g_Lp + pbase * 128;

    #pragma unroll
    for (int m2 = 0; m2 < 2; m2++) {
        const int pr = w * 32 + m2 * 16 + g;
        if (tq == 0) {
            Lp[pr]     = l[m2][0];
            Lp[pr + 8] = l[m2][1];
        }
        #pragma unroll
        for (int nt = 0; nt < 8; nt++) {
            float2 v0 = make_float2(o[m2][nt][0], o[m2][nt][1]);
            float2 v1 = make_float2(o[m2][nt][2], o[m2][nt][3]);
            *(float2*)(Op + (size_t)pr * DOUT_ + nt * 8 + tq * 2)       = v0;
            *(float2*)(Op + (size_t)(pr + 8) * DOUT_ + nt * 8 + tq * 2) = v1;
        }
    }
}

// ---------------------------------------------------------------------------
// Combine (exact R11 version — best measured at 9.76us):
// out[row] = sum_c Op[c][row] / sum_c Lp[c][row]. Simple serial chunk loop,
// 2 threads per row x 32 cols.
// ---------------------------------------------------------------------------
__global__ __launch_bounds__(256) void attn_combine_kernel(float* __restrict__ out) {
    const int t   = blockIdx.x * 256 + threadIdx.x;
    const int R   = t >> 1;
    const int hc  = (t & 1) * 32;
    const int b   = R >> 12;
    const int q   = R & 4095;
    const int p   = q >> 7;
    const int rw  = q & 127;
    const int nch = (p >> 2) + 1;

    const size_t pb = (size_t)(b * NPAIR + p) * 8;
    float4 acc[8];
    #pragma unroll
    for (int j = 0; j < 8; j++) acc[j] = make_float4(0.f, 0.f, 0.f, 0.f);
    float lsum = 0.0f;

    for (int c = 0; c < nch; c++) {
        const float* Op = g_Op + (pb + c) * 128 * DOUT_ + (size_t)rw * DOUT_ + hc;
        lsum += g_Lp[(pb + c) * 128 + rw];
        #pragma unroll
        for (int j = 0; j < 8; j++) {
            float4 v = *(const float4*)(Op + j * 4);
            acc[j].x += v.x; acc[j].y += v.y; acc[j].z += v.z; acc[j].w += v.w;
        }
    }

    const float inv = 1.0f / lsum;
    float* dst = out + (size_t)R * DOUT_ + hc;
    #pragma unroll
    for (int j = 0; j < 8; j++) {
        float4 v = make_float4(acc[j].x * inv, acc[j].y * inv,
                               acc[j].z * inv, acc[j].w * inv);
        *(float4*)(dst + j * 4) = v;
    }
}

// ---------------------------------------------------------------------------
extern "C" void kernel_launch(void* const* d_in, const int* in_sizes, int n_in,
                              void* d_out, int out_size) {
    const float* x_k = (const float*)d_in[0];
    const float* x_v = (const float*)d_in[1];
    const float* x_q = (const float*)d_in[2];
    const float* Wk  = (const float*)d_in[3];
    const float* Wq  = (const float*)d_in[4];
    const float* Wv  = (const float*)d_in[5];
    float* out = (float*)d_out;

    cudaFuncSetAttribute(proj_mma_kernel, cudaFuncAttributeMaxDynamicSharedMemorySize,
                         PROJ_SMEM_BYTES);
    cudaFuncSetAttribute(attn_part_kernel, cudaFuncAttributeMaxDynamicSharedMemorySize,
                         ATTN_SMEM_BYTES);

    w_prep_kernel<<<96, 256>>>(Wk, Wv, Wq);
    proj_mma_kernel<<<dim3(128, 3), 128, PROJ_SMEM_BYTES>>>(x_k, x_v, x_q);
    attn_part_kernel<<<NBLKS, 128, ATTN_SMEM_BYTES>>>();
    attn_combine_kernel<<<128, 256>>>(out);
}

// round 16
// speedup vs baseline: 1.4198x; 1.0464x over previous
#include <cuda_runtime.h>
#include <math.h>

#define B_    4
#define S_    4096
#define DIN_  512
#define DOUT_ 64
#define SCALE 0.015625f   // 1/sqrt(4096)

#define NPAIR   32
#define CHUNK_T 8
#define BLKS_PB 144
#define NBLKS   (B_ * BLKS_PB)      // 576

// Scratch. g_K/g_V stored with intra-row XOR swizzle:
//   word(row, d) = row*64 + (d ^ (((row&3)<<3) | (row&4)))
// g_Q plain row-major. All values tf32-rounded fp32.
__device__ float g_Q[B_ * S_ * DOUT_];
__device__ float g_K[B_ * S_ * DOUT_];
__device__ float g_V[B_ * S_ * DOUT_];
__device__ float g_Op[B_ * NPAIR * 8 * 128 * DOUT_];
__device__ float g_Lp[B_ * NPAIR * 8 * 128];
__device__ unsigned g_Wr[3 * DIN_ * DOUT_];   // W pre-rounded to tf32 bits

__device__ __forceinline__ unsigned f2tf32(float x) {
    unsigned r;
    asm("cvt.rna.tf32.f32 %0, %1;" : "=r"(r) : "f"(x));
    return r;
}

__device__ __forceinline__ void mma_tf32(float c[4], const unsigned a[4],
                                         unsigned b0, unsigned b1) {
    asm volatile(
        "mma.sync.aligned.m16n8k8.row.col.f32.tf32.tf32.f32 "
        "{%0,%1,%2,%3},{%4,%5,%6,%7},{%8,%9},{%0,%1,%2,%3};"
        : "+f"(c[0]), "+f"(c[1]), "+f"(c[2]), "+f"(c[3])
        : "r"(a[0]), "r"(a[1]), "r"(a[2]), "r"(a[3]), "r"(b0), "r"(b1));
}

// ---- bulk copy + mbarrier helpers -----------------------------------------
__device__ __forceinline__ void mbar_init(void* p, unsigned cnt) {
    unsigned a = (unsigned)__cvta_generic_to_shared(p);
    asm volatile("mbarrier.init.shared.b64 [%0], %1;" :: "r"(a), "r"(cnt) : "memory");
}
__device__ __forceinline__ void mbar_expect_tx(void* p, unsigned bytes) {
    unsigned a = (unsigned)__cvta_generic_to_shared(p);
    asm volatile("mbarrier.arrive.expect_tx.shared.b64 _, [%0], %1;"
                 :: "r"(a), "r"(bytes) : "memory");
}
__device__ __forceinline__ void bulk_g2s(void* sdst, const void* gsrc,
                                         unsigned bytes, void* mbar) {
    unsigned d = (unsigned)__cvta_generic_to_shared(sdst);
    unsigned m = (unsigned)__cvta_generic_to_shared(mbar);
    asm volatile(
        "cp.async.bulk.shared::cta.global.mbarrier::complete_tx::bytes [%0], [%1], %2, [%3];"
        :: "r"(d), "l"(gsrc), "r"(bytes), "r"(m) : "memory");
}
__device__ __forceinline__ void mbar_wait(void* p, unsigned phase) {
    unsigned a = (unsigned)__cvta_generic_to_shared(p);
    asm volatile(
        "{\n\t.reg .pred P;\n\t"
        "W%=:\n\t"
        "mbarrier.try_wait.parity.acquire.cta.shared::cta.b64 P, [%0], %1;\n\t"
        "@!P bra W%=;\n\t}"
        :: "r"(a), "r"(phase) : "memory");
}

// ---------------------------------------------------------------------------
// W prep: rna-round weights once (bit-identical to rounding on every use).
// ---------------------------------------------------------------------------
__global__ __launch_bounds__(256) void w_prep_kernel(
        const float* __restrict__ w0, const float* __restrict__ w1,
        const float* __restrict__ w2) {
    const int t = blockIdx.x * 256 + threadIdx.x;
    const int which = t >> 13;
    const int idx = t & 8191;
    const float* W = (which == 0) ? w0 : (which == 1) ? w1 : w2;
    float4 v = ((const float4*)W)[idx];
    uint4 u;
    u.x = f2tf32(v.x); u.y = f2tf32(v.y); u.z = f2tf32(v.z); u.w = f2tf32(v.w);
    ((uint4*)(g_Wr + which * DIN_ * DOUT_))[idx] = u;
}

// ---------------------------------------------------------------------------
// Projection GEMM (exact R12 version — best measured). 128-row blocks,
// 128 threads = 4 warps x 32 rows (2 m16 blocks each).
// which: 0 -> g_K (swizzled), 1 -> g_V (swizzled), 2 -> g_Q (plain).
// ---------------------------------------------------------------------------
#define PXS 36
#define PWS 72
#define PROJ_SMEM_BYTES ((2 * 128 * PXS + 2 * 32 * PWS) * 4)   // 55296

__global__ __launch_bounds__(128) void proj_mma_kernel(
        const float* __restrict__ x0, const float* __restrict__ x1,
        const float* __restrict__ x2) {
    extern __shared__ float smp[];
    float*    Xb[2] = { smp, smp + 128 * PXS };
    unsigned* Wb[2] = { (unsigned*)(smp + 2 * 128 * PXS),
                        (unsigned*)(smp + 2 * 128 * PXS) + 32 * PWS };

    const int which = blockIdx.y;
    const float* X = (which == 0) ? x0 : (which == 1) ? x1 : x2;
    const unsigned* Wr = g_Wr + which * DIN_ * DOUT_;
    float* dst = (which == 0) ? g_K : (which == 1) ? g_V : g_Q;

    const int m0   = blockIdx.x * 128;
    const int tid  = threadIdx.x;
    const int w    = tid >> 5;
    const int lane = tid & 31;
    const int g    = lane >> 2;
    const int tq   = lane & 3;

    float4 xr[8];
    uint4  wr[4];

    #define LDG_CHUNK(k0_) do {                                               \
        _Pragma("unroll")                                                     \
        for (int i_ = 0; i_ < 8; i_++) {                                      \
            int f_ = tid + i_ * 128;                                          \
            xr[i_] = *(const float4*)(X + (size_t)(m0 + (f_ >> 3)) * DIN_     \
                                        + (k0_) + (f_ & 7) * 4);              \
        }                                                                     \
        _Pragma("unroll")                                                     \
        for (int i_ = 0; i_ < 4; i_++) {                                      \
            int f_ = tid + i_ * 128;                                          \
            wr[i_] = *(const uint4*)(Wr + (size_t)((k0_) + (f_ >> 4)) * DOUT_ \
                                        + (f_ & 15) * 4);                     \
        }                                                                     \
    } while (0)

    #define STS_CHUNK(buf_) do {                                              \
        _Pragma("unroll")                                                     \
        for (int i_ = 0; i_ < 8; i_++) {                                      \
            int f_ = tid + i_ * 128;                                          \
            *(float4*)(Xb[buf_] + (f_ >> 3) * PXS + (f_ & 7) * 4) = xr[i_];   \
        }                                                                     \
        _Pragma("unroll")                                                     \
        for (int i_ = 0; i_ < 4; i_++) {                                      \
            int f_ = tid + i_ * 128;                                          \
            *(uint4*)(Wb[buf_] + (f_ >> 4) * PWS + (f_ & 15) * 4) = wr[i_];   \
        }                                                                     \
    } while (0)

    LDG_CHUNK(0);
    STS_CHUNK(0);
    LDG_CHUNK(32);
    __syncthreads();

    float acc[2][8][4];
    #pragma unroll
    for (int m2 = 0; m2 < 2; m2++)
        #pragma unroll
        for (int nt = 0; nt < 8; nt++)
            #pragma unroll
            for (int j = 0; j < 4; j++) acc[m2][nt][j] = 0.0f;

    #pragma unroll 2
    for (int c = 0; c < 16; c++) {
        const int cur = c & 1;
        const float* Xc = Xb[cur];
        const unsigned* Wc = Wb[cur];

        #pragma unroll
        for (int kk = 0; kk < 4; kk++) {
            unsigned a0[4], a1[4];
            const int q0 = w * 32 + g;
            a0[0] = f2tf32(Xc[q0 * PXS + kk * 8 + tq]);
            a0[1] = f2tf32(Xc[(q0 + 8) * PXS + kk * 8 + tq]);
            a0[2] = f2tf32(Xc[q0 * PXS + kk * 8 + tq + 4]);
            a0[3] = f2tf32(Xc[(q0 + 8) * PXS + kk * 8 + tq + 4]);
            a1[0] = f2tf32(Xc[(q0 + 16) * PXS + kk * 8 + tq]);
            a1[1] = f2tf32(Xc[(q0 + 24) * PXS + kk * 8 + tq]);
            a1[2] = f2tf32(Xc[(q0 + 16) * PXS + kk * 8 + tq + 4]);
            a1[3] = f2tf32(Xc[(q0 + 24) * PXS + kk * 8 + tq + 4]);
            #pragma unroll
            for (int nt = 0; nt < 8; nt++) {
                unsigned b0 = Wc[(kk * 8 + tq) * PWS + nt * 8 + g];
                unsigned b1 = Wc[(kk * 8 + tq + 4) * PWS + nt * 8 + g];
                mma_tf32(acc[0][nt], a0, b0, b1);
                mma_tf32(acc[1][nt], a1, b0, b1);
            }
        }

        if (c < 15) {
            STS_CHUNK(cur ^ 1);
            if (c < 14) LDG_CHUNK((c + 2) * 32);
            __syncthreads();
        }
    }
    #undef LDG_CHUNK
    #undef STS_CHUNK

    #pragma unroll
    for (int m2 = 0; m2 < 2; m2++) {
        #pragma unroll
        for (int nt = 0; nt < 8; nt++) {
            #pragma unroll
            for (int rr = 0; rr < 2; rr++) {
                const int row = m0 + w * 32 + m2 * 16 + g + rr * 8;
                const int d   = nt * 8 + tq * 2;
                float2 v;
                v.x = __uint_as_float(f2tf32(acc[m2][nt][rr * 2 + 0]));
                v.y = __uint_as_float(f2tf32(acc[m2][nt][rr * 2 + 1]));
                int dd = (which == 2) ? d : (d ^ (((row & 3) << 3) | (row & 4)));
                *(float2*)(dst + (size_t)row * DOUT_ + dd) = v;
            }
        }
    }
}

// ---------------------------------------------------------------------------
// Split-K flash attention partial (exact R12 version — best measured).
// ---------------------------------------------------------------------------
#define PSS 68
#define ATTN_SMEM_BYTES ((4 * 4096 + 128 * PSS) * 4 + 16)   // 100368

__global__ __launch_bounds__(128) void attn_part_kernel() {
    extern __shared__ unsigned sm[];
    unsigned* Kb[2] = { sm,        sm + 4096 };
    unsigned* Vb[2] = { sm + 8192, sm + 12288 };
    unsigned* Ps    = sm + 16384;
    unsigned long long* mb = (unsigned long long*)(Ps + 128 * PSS);

    const int tid  = threadIdx.x;
    const int w    = tid >> 5;
    const int lane = tid & 31;
    const int g    = lane >> 2;
    const int tq   = lane & 3;

    const int b = blockIdx.x / BLKS_PB;
    int f = blockIdx.x % BLKS_PB;
    int gp = 0;
    while (f >= 2 * (gp + 1) * (gp + 2)) gp++;
    const int r  = f - 2 * gp * (gp + 1);
    const int p  = 4 * gp + r / (gp + 1);
    const int c  = r % (gp + 1);
    const int ntiles = min(CHUNK_T, 2 * p + 2 - CHUNK_T * c);

    const float* Qg = g_Q + (size_t)b * S_ * DOUT_ + (size_t)p * 128 * DOUT_;
    const float* Kg = g_K + (size_t)b * S_ * DOUT_ + (size_t)c * CHUNK_T * 64 * DOUT_;
    const float* Vg = g_V + (size_t)b * S_ * DOUT_ + (size_t)c * CHUNK_T * 64 * DOUT_;

    #define ISSUE(kt_) do {                                                   \
        int buf_ = (kt_) & 1;                                                 \
        mbar_expect_tx(mb + buf_, 32768u);                                    \
        bulk_g2s(Kb[buf_], Kg + (size_t)(kt_) * 64 * DOUT_, 16384u, mb + buf_);\
        bulk_g2s(Vb[buf_], Vg + (size_t)(kt_) * 64 * DOUT_, 16384u, mb + buf_);\
    } while (0)

    if (tid == 0) { mbar_init(mb, 1); mbar_init(mb + 1, 1); }
    __syncthreads();
    if (tid == 0) { ISSUE(0); if (ntiles > 1) ISSUE(1); }

    #pragma unroll
    for (int t = 0; t < 16; t++) {
        int ff = tid + t * 128;
        int rr = ff >> 4, s4 = ff & 15;
        float4 qv = *(const float4*)(Qg + (size_t)rr * DOUT_ + s4 * 4);
        unsigned* d = Ps + rr * PSS + s4 * 4;
        d[0] = __float_as_uint(qv.x); d[1] = __float_as_uint(qv.y);
        d[2] = __float_as_uint(qv.z); d[3] = __float_as_uint(qv.w);
    }
    __syncthreads();

    unsigned qa[2][8][4];
    #pragma unroll
    for (int m2 = 0; m2 < 2; m2++) {
        const int q0 = w * 32 + m2 * 16 + g;
        #pragma unroll
        for (int kk = 0; kk < 8; kk++) {
            qa[m2][kk][0] = Ps[q0 * PSS + kk * 8 + tq];
            qa[m2][kk][1] = Ps[(q0 + 8) * PSS + kk * 8 + tq];
            qa[m2][kk][2] = Ps[q0 * PSS + kk * 8 + tq + 4];
            qa[m2][kk][3] = Ps[(q0 + 8) * PSS + kk * 8 + tq + 4];
        }
    }

    float o[2][8][4];
    #pragma unroll
    for (int m2 = 0; m2 < 2; m2++)
        #pragma unroll
        for (int nt = 0; nt < 8; nt++)
            #pragma unroll
            for (int j = 0; j < 4; j++) o[m2][nt][j] = 0.0f;
    float l[2][2] = {{0.f, 0.f}, {0.f, 0.f}};

    const int swk  = ((g & 3) << 3) | (g & 4);
    const int swv0 = tq << 3;
    const int swv1 = (tq << 3) | 4;

    #pragma unroll 1
    for (int kt = 0; kt < ntiles; kt++) {
        const int kbase = (c * CHUNK_T + kt) * 64;

        mbar_wait(mb + (kt & 1), (kt >> 1) & 1);
        const unsigned* Ks = Kb[kt & 1];
        const unsigned* Vs = Vb[kt & 1];

        float sacc[2][8][4];
        #pragma unroll
        for (int m2 = 0; m2 < 2; m2++)
            #pragma unroll
            for (int nt = 0; nt < 8; nt++)
                #pragma unroll
                for (int j = 0; j < 4; j++) sacc[m2][nt][j] = 0.0f;

        #pragma unroll
        for (int kk = 0; kk < 8; kk++) {
            #pragma unroll
            for (int nt = 0; nt < 8; nt++) {
                unsigned b0 = Ks[(nt * 8 + g) * 64 + ((kk * 8 + tq) ^ swk)];
                unsigned b1 = Ks[(nt * 8 + g) * 64 + ((kk * 8 + tq + 4) ^ swk)];
                mma_tf32(sacc[0][nt], qa[0][kk], b0, b1);
                mma_tf32(sacc[1][nt], qa[1][kk], b0, b1);
            }
        }

        #pragma unroll
        for (int m2 = 0; m2 < 2; m2++) {
            const int pr    = w * 32 + m2 * 16 + g;
            const int row0g = p * 128 + pr;
            const int row1g = row0g + 8;
            const bool need_mask = (kbase + 63 > row0g);
            #pragma unroll
            for (int nt = 0; nt < 8; nt++) {
                float s00 = sacc[m2][nt][0] * SCALE;
                float s01 = sacc[m2][nt][1] * SCALE;
                float s10 = sacc[m2][nt][2] * SCALE;
                float s11 = sacc[m2][nt][3] * SCALE;
                float p00 = fmaf(s00, fmaf(s00, 0.5f, 1.0f), 1.0f);
                float p01 = fmaf(s01, fmaf(s01, 0.5f, 1.0f), 1.0f);
                float p10 = fmaf(s10, fmaf(s10, 0.5f, 1.0f), 1.0f);
                float p11 = fmaf(s11, fmaf(s11, 0.5f, 1.0f), 1.0f);
                if (need_mask) {
                    int c0 = kbase + nt * 8 + tq * 2;
                    int c1 = c0 + 1;
                    if (c0 > row0g) p00 = 0.0f;
                    if (c1 > row0g) p01 = 0.0f;
                    if (c0 > row1g) p10 = 0.0f;
                    if (c1 > row1g) p11 = 0.0f;
                }
                l[m2][0] += p00 + p01;
                l[m2][1] += p10 + p11;
                uint2 u0; u0.x = f2tf32(p00); u0.y = f2tf32(p01);
                uint2 u1; u1.x = f2tf32(p10); u1.y = f2tf32(p11);
                *(uint2*)(Ps + pr * PSS + nt * 8 + tq * 2)       = u0;
                *(uint2*)(Ps + (pr + 8) * PSS + nt * 8 + tq * 2) = u1;
            }
        }
        __syncwarp();

        #pragma unroll
        for (int kk = 0; kk < 8; kk++) {
            unsigned pa0[4], pa1[4];
            const int pr0 = w * 32 + g;
            const int pr1 = pr0 + 16;
            pa0[0] = Ps[pr0 * PSS + kk * 8 + tq];
            pa0[1] = Ps[(pr0 + 8) * PSS + kk * 8 + tq];
            pa0[2] = Ps[pr0 * PSS + kk * 8 + tq + 4];
            pa0[3] = Ps[(pr0 + 8) * PSS + kk * 8 + tq + 4];
            pa1[0] = Ps[pr1 * PSS + kk * 8 + tq];
            pa1[1] = Ps[(pr1 + 8) * PSS + kk * 8 + tq];
            pa1[2] = Ps[pr1 * PSS + kk * 8 + tq + 4];
            pa1[3] = Ps[(pr1 + 8) * PSS + kk * 8 + tq + 4];
            #pragma unroll
            for (int nt = 0; nt < 8; nt++) {
                unsigned b0 = Vs[(kk * 8 + tq) * 64     + ((nt * 8 + g) ^ swv0)];
                unsigned b1 = Vs[(kk * 8 + tq + 4) * 64 + ((nt * 8 + g) ^ swv1)];
                mma_tf32(o[0][nt], pa0, b0, b1);
                mma_tf32(o[1][nt], pa1, b0, b1);
            }
        }

        __syncthreads();
        if (tid == 0 && kt + 2 < ntiles) ISSUE(kt + 2);
    }
    #undef ISSUE

    #pragma unroll
    for (int m2 = 0; m2 < 2; m2++) {
        #pragma unroll
        for (int off = 1; off <= 2; off <<= 1) {
            l[m2][0] += __shfl_xor_sync(0xffffffffu, l[m2][0], off);
            l[m2][1] += __shfl_xor_sync(0xffffffffu, l[m2][1], off);
        }
    }

    const size_t pbase = ((size_t)(b * NPAIR + p) * 8 + c);
    float* Op = g_Op + pbase * 128 * DOUT_;
    float* Lp = g_Lp + pbase * 128;

    #pragma unroll
    for (int m2 = 0; m2 < 2; m2++) {
        const int pr = w * 32 + m2 * 16 + g;
        if (tq == 0) {
            Lp[pr]     = l[m2][0];
            Lp[pr + 8] = l[m2][1];
        }
        #pragma unroll
        for (int nt = 0; nt < 8; nt++) {
            float2 v0 = make_float2(o[m2][nt][0], o[m2][nt][1]);
            float2 v1 = make_float2(o[m2][nt][2], o[m2][nt][3]);
            *(float2*)(Op + (size_t)pr * DOUT_ + nt * 8 + tq * 2)       = v0;
            *(float2*)(Op + (size_t)(pr + 8) * DOUT_ + nt * 8 + tq * 2) = v1;
        }
    }
}

// ---------------------------------------------------------------------------
// Combine (exact R11 version — best measured 9.76us): 4 threads per row
// (16 cols each), simple serial chunk loop, grid 256 x 256 thr.
// ---------------------------------------------------------------------------
__global__ __launch_bounds__(256) void attn_combine_kernel(float* __restrict__ out) {
    const int t   = blockIdx.x * 256 + threadIdx.x;
    const int R   = t >> 2;
    const int hc  = (t & 3) * 16;
    const int b   = R >> 12;
    const int q   = R & 4095;
    const int p   = q >> 7;
    const int rw  = q & 127;
    const int nch = (p >> 2) + 1;

    const size_t pb = (size_t)(b * NPAIR + p) * 8;
    float4 acc[4];
    #pragma unroll
    for (int j = 0; j < 4; j++) acc[j] = make_float4(0.f, 0.f, 0.f, 0.f);
    float lsum = 0.0f;

    for (int c = 0; c < nch; c++) {
        const float* Op = g_Op + (pb + c) * 128 * DOUT_ + (size_t)rw * DOUT_ + hc;
        lsum += g_Lp[(pb + c) * 128 + rw];
        #pragma unroll
        for (int j = 0; j < 4; j++) {
            float4 v = *(const float4*)(Op + j * 4);
            acc[j].x += v.x; acc[j].y += v.y; acc[j].z += v.z; acc[j].w += v.w;
        }
    }

    const float inv = 1.0f / lsum;
    float* dst = out + (size_t)R * DOUT_ + hc;
    #pragma unroll
    for (int j = 0; j < 4; j++) {
        float4 v = make_float4(acc[j].x * inv, acc[j].y * inv,
                               acc[j].z * inv, acc[j].w * inv);
        *(float4*)(dst + j * 4) = v;
    }
}

// ---------------------------------------------------------------------------
extern "C" void kernel_launch(void* const* d_in, const int* in_sizes, int n_in,
                              void* d_out, int out_size) {
    const float* x_k = (const float*)d_in[0];
    const float* x_v = (const float*)d_in[1];
    const float* x_q = (const float*)d_in[2];
    const float* Wk  = (const float*)d_in[3];
    const float* Wq  = (const float*)d_in[4];
    const float* Wv  = (const float*)d_in[5];
    float* out = (float*)d_out;

    cudaFuncSetAttribute(proj_mma_kernel, cudaFuncAttributeMaxDynamicSharedMemorySize,
                         PROJ_SMEM_BYTES);
    cudaFuncSetAttribute(attn_part_kernel, cudaFuncAttributeMaxDynamicSharedMemorySize,
                         ATTN_SMEM_BYTES);

    w_prep_kernel<<<96, 256>>>(Wk, Wv, Wq);
    proj_mma_kernel<<<dim3(128, 3), 128, PROJ_SMEM_BYTES>>>(x_k, x_v, x_q);
    attn_part_kernel<<<NBLKS, 128, ATTN_SMEM_BYTES>>>();
    attn_combine_kernel<<<256, 256>>>(out);
}